// round 3
// baseline (speedup 1.0000x reference)
#include <cuda_runtime.h>

#define NF 512
#define NH 16
#define NC 40
#define NMAX 100000

// ---- scratch (static device globals; no allocations allowed) ----
__device__ float g_deg[NMAX];
__device__ float g_dinv[NMAX];
__device__ float g_h1[NMAX * NH];   // x @ W1 + b1
__device__ float g_a1[NMAX * NH];   // aggregated + relu
__device__ float g_h2[NMAX * NC];   // a1 @ W2 + b2
__device__ float g_a2[NMAX * NC];   // aggregated logits

// ---------------------------------------------------------------------------
// init: deg = 1 (self loop), zero accumulators
// ---------------------------------------------------------------------------
__global__ void k_init(int n) {
    int i = blockIdx.x * blockDim.x + threadIdx.x;
    if (i < n) g_deg[i] = 1.0f;
    if (i < n * NH) g_a1[i] = 0.0f;
    if (i < n * NC) g_a2[i] = 0.0f;
}

// ---------------------------------------------------------------------------
// degree over src (row) — exact (+1.0 adds are order-independent)
// ---------------------------------------------------------------------------
__global__ void k_deg(const int* __restrict__ src, int E) {
    int e = blockIdx.x * blockDim.x + threadIdx.x;
    if (e < E) atomicAdd(&g_deg[src[e]], 1.0f);
}

__global__ void k_dinv(int n) {
    int i = blockIdx.x * blockDim.x + threadIdx.x;
    if (i < n) g_dinv[i] = rsqrtf(g_deg[i]);
}

// ---------------------------------------------------------------------------
// GEMM1: h1 = x @ W1 + b1   (thread per row, W1 broadcast from smem)
// ---------------------------------------------------------------------------
__global__ void k_gemm1(const float* __restrict__ x,
                        const float* __restrict__ W1,
                        const float* __restrict__ b1, int n) {
    __shared__ float sW[NF * NH];  // 32 KB
    for (int i = threadIdx.x; i < NF * NH; i += blockDim.x) sW[i] = W1[i];
    __syncthreads();

    int row = blockIdx.x * blockDim.x + threadIdx.x;
    if (row >= n) return;

    float acc[NH];
#pragma unroll
    for (int c = 0; c < NH; c++) acc[c] = __ldg(&b1[c]);

    const float4* xr = (const float4*)(x + (size_t)row * NF);
    const float4* sW4 = (const float4*)sW;

#pragma unroll 4
    for (int k4 = 0; k4 < NF / 4; k4++) {
        float4 xv = xr[k4];
#pragma unroll
        for (int j = 0; j < 4; j++) {
            float xs = (&xv.x)[j];
            int k = k4 * 4 + j;
#pragma unroll
            for (int c4 = 0; c4 < NH / 4; c4++) {
                float4 w = sW4[k * (NH / 4) + c4];
                acc[c4 * 4 + 0] += xs * w.x;
                acc[c4 * 4 + 1] += xs * w.y;
                acc[c4 * 4 + 2] += xs * w.z;
                acc[c4 * 4 + 3] += xs * w.w;
            }
        }
    }

    float* hr = g_h1 + (size_t)row * NH;
#pragma unroll
    for (int c = 0; c < NH; c++) hr[c] = acc[c];
}

// ---------------------------------------------------------------------------
// Aggregation layer 1 (push, atomic): 16 lanes per edge
// ---------------------------------------------------------------------------
__global__ void k_agg1(const int* __restrict__ src,
                       const int* __restrict__ dst, int E) {
    int g = (blockIdx.x * blockDim.x + threadIdx.x) >> 4;
    int c = threadIdx.x & 15;
    if (g >= E) return;
    int s = src[g];
    int d = dst[g];
    float w = g_dinv[s] * g_dinv[d];
    atomicAdd(&g_a1[d * NH + c], w * g_h1[s * NH + c]);
}

// self-loop term + relu
__global__ void k_post1(int n) {
    int i = blockIdx.x * blockDim.x + threadIdx.x;
    if (i >= n * NH) return;
    int d = i >> 4;
    float di = g_dinv[d];
    float v = g_a1[i] + di * di * g_h1[i];
    g_a1[i] = v > 0.0f ? v : 0.0f;
}

// ---------------------------------------------------------------------------
// GEMM2: h2 = a1 @ W2 + b2   (thread per row)
// ---------------------------------------------------------------------------
__global__ void k_gemm2(const float* __restrict__ W2,
                        const float* __restrict__ b2, int n) {
    __shared__ float sW[NH * NC];
    __shared__ float sb[NC];
    for (int i = threadIdx.x; i < NH * NC; i += blockDim.x) sW[i] = W2[i];
    for (int i = threadIdx.x; i < NC; i += blockDim.x) sb[i] = b2[i];
    __syncthreads();

    int row = blockIdx.x * blockDim.x + threadIdx.x;
    if (row >= n) return;

    float acc[NC];
#pragma unroll
    for (int c = 0; c < NC; c++) acc[c] = sb[c];

    const float* ar = g_a1 + (size_t)row * NH;
    const float4* sW4 = (const float4*)sW;
#pragma unroll
    for (int k = 0; k < NH; k++) {
        float av = ar[k];
#pragma unroll
        for (int c4 = 0; c4 < NC / 4; c4++) {
            float4 w = sW4[k * (NC / 4) + c4];
            acc[c4 * 4 + 0] += av * w.x;
            acc[c4 * 4 + 1] += av * w.y;
            acc[c4 * 4 + 2] += av * w.z;
            acc[c4 * 4 + 3] += av * w.w;
        }
    }
    float* hr = g_h2 + (size_t)row * NC;
#pragma unroll
    for (int c = 0; c < NC; c++) hr[c] = acc[c];
}

// ---------------------------------------------------------------------------
// Aggregation layer 2 (push, atomic): one warp per edge (40 features)
// lane l handles col l, and col 32+l for l < 8
// ---------------------------------------------------------------------------
__global__ void k_agg2(const int* __restrict__ src,
                       const int* __restrict__ dst, int E) {
    int e = (blockIdx.x * blockDim.x + threadIdx.x) >> 5;
    int l = threadIdx.x & 31;
    if (e >= E) return;
    int s = src[e];
    int d = dst[e];
    float w = g_dinv[s] * g_dinv[d];
    const float* hs = g_h2 + (size_t)s * NC;
    float* ad = g_a2 + (size_t)d * NC;
    atomicAdd(&ad[l], w * hs[l]);
    if (l < 8) atomicAdd(&ad[32 + l], w * hs[32 + l]);
}

// self-loop term layer 2 (no relu)
__global__ void k_post2(int n) {
    int i = blockIdx.x * blockDim.x + threadIdx.x;
    if (i >= n * NC) return;
    int d = i / NC;
    float di = g_dinv[d];
    g_a2[i] = g_a2[i] + di * di * g_h2[i];
}

// ---------------------------------------------------------------------------
// log_softmax over 40 classes: one warp per row
// ---------------------------------------------------------------------------
__global__ void k_softmax(float* __restrict__ out, int n) {
    int r = (blockIdx.x * blockDim.x + threadIdx.x) >> 5;
    int l = threadIdx.x & 31;
    if (r >= n) return;
    const float* ar = g_a2 + (size_t)r * NC;
    float v0 = ar[l];
    float v1 = (l < 8) ? ar[32 + l] : -1e30f;
    float m = fmaxf(v0, v1);
#pragma unroll
    for (int o = 16; o > 0; o >>= 1) m = fmaxf(m, __shfl_xor_sync(0xffffffffu, m, o));
    float s = expf(v0 - m) + ((l < 8) ? expf(v1 - m) : 0.0f);
#pragma unroll
    for (int o = 16; o > 0; o >>= 1) s += __shfl_xor_sync(0xffffffffu, s, o);
    float lse = m + logf(s);
    float* orow = out + (size_t)r * NC;
    orow[l] = v0 - lse;
    if (l < 8) orow[32 + l] = v1 - lse;
}

// ---------------------------------------------------------------------------
extern "C" void kernel_launch(void* const* d_in, const int* in_sizes, int n_in,
                              void* d_out, int out_size) {
    const float* x = (const float*)d_in[0];
    const int* ei = (const int*)d_in[1];     // int32: JAX x64 disabled downcasts int64
    const float* W1 = (const float*)d_in[2];
    const float* b1 = (const float*)d_in[3];
    const float* W2 = (const float*)d_in[4];
    const float* b2 = (const float*)d_in[5];
    float* out = (float*)d_out;

    int n = in_sizes[0] / NF;           // 100000
    int E = in_sizes[1] / 2;            // 3200000
    const int* src = ei;
    const int* dst = ei + E;

    const int B = 256;
    k_init<<<(n * NC + B - 1) / B, B>>>(n);
    k_deg<<<(E + B - 1) / B, B>>>(src, E);
    k_dinv<<<(n + B - 1) / B, B>>>(n);
    k_gemm1<<<(n + 127) / 128, 128>>>(x, W1, b1, n);
    {
        long long th = (long long)E * 16;
        k_agg1<<<(unsigned)((th + B - 1) / B), B>>>(src, dst, E);
    }
    k_post1<<<(n * NH + B - 1) / B, B>>>(n);
    k_gemm2<<<(n + 127) / 128, 128>>>(W2, b2, n);
    {
        long long th = (long long)E * 32;
        k_agg2<<<(unsigned)((th + B - 1) / B), B>>>(src, dst, E);
    }
    k_post2<<<(n * NC + B - 1) / B, B>>>(n);
    k_softmax<<<(n * 32 + B - 1) / B, B>>>(out, n);
}

// round 4
// speedup vs baseline: 2.0961x; 2.0961x over previous
#include <cuda_runtime.h>

#define NF 512
#define NH 16
#define NC 40
#define NMAX 100000

// ---- scratch (static device globals; no allocations allowed) ----
__device__ float g_deg[NMAX];
__device__ float g_dinv[NMAX];
__device__ float g_h1[NMAX * NH];    // x @ W1 + b1
__device__ float g_a1[NMAX * NH];    // layer-1 aggregated + relu
__device__ float g_agg2[NMAX * NH];  // layer-2 aggregation of a1 (pre-W2!)
__device__ float g_nsum[NMAX];       // sum of norm over in-edges (for bias)

// ---------------------------------------------------------------------------
// init: deg = 1 (self loop), zero accumulators
// ---------------------------------------------------------------------------
__global__ void k_init(int n) {
    int i = blockIdx.x * blockDim.x + threadIdx.x;
    if (i < n) { g_deg[i] = 1.0f; g_nsum[i] = 0.0f; }
    if (i < n * NH) { g_a1[i] = 0.0f; g_agg2[i] = 0.0f; }
}

// ---------------------------------------------------------------------------
// degree over src (row) — exact (+1.0 adds are order-independent)
// ---------------------------------------------------------------------------
__global__ void k_deg(const int* __restrict__ src, int E) {
    int e = blockIdx.x * blockDim.x + threadIdx.x;
    if (e < E) atomicAdd(&g_deg[src[e]], 1.0f);
}

__global__ void k_dinv(int n) {
    int i = blockIdx.x * blockDim.x + threadIdx.x;
    if (i < n) g_dinv[i] = rsqrtf(g_deg[i]);
}

// ---------------------------------------------------------------------------
// GEMM1: h1 = x @ W1 + b1
// block = 128 threads = 128 rows; x staged through smem in k-tiles of 64,
// loads fully coalesced (scalar, 1 line/request), reads conflict-free
// (row stride 65 -> bank = (tid + k) % 32). W broadcast via __ldg (L1-resident).
// ---------------------------------------------------------------------------
__global__ void __launch_bounds__(128) k_gemm1(const float* __restrict__ x,
                                               const float* __restrict__ W1,
                                               const float* __restrict__ b1, int n) {
    __shared__ float xt[128 * 65];  // 33.3 KB
    int tid = threadIdx.x;
    int row0 = blockIdx.x * 128;

    float acc[NH];
#pragma unroll
    for (int c = 0; c < NH; c++) acc[c] = __ldg(&b1[c]);

    for (int t = 0; t < 8; t++) {
        int k0 = t * 64;
        __syncthreads();  // protect previous tile reads
#pragma unroll 8
        for (int i = 0; i < 64; i++) {
            int e = i * 128 + tid;
            int rr = e >> 6, cc = e & 63;
            int gr = row0 + rr;
            float v = (gr < n) ? x[(size_t)gr * NF + k0 + cc] : 0.0f;
            xt[rr * 65 + cc] = v;
        }
        __syncthreads();

        const float4* W4 = (const float4*)(W1 + (size_t)k0 * NH);
#pragma unroll 8
        for (int k = 0; k < 64; k++) {
            float xs = xt[tid * 65 + k];
            float4 w0 = __ldg(W4 + k * 4 + 0);
            float4 w1 = __ldg(W4 + k * 4 + 1);
            float4 w2 = __ldg(W4 + k * 4 + 2);
            float4 w3 = __ldg(W4 + k * 4 + 3);
            acc[0]  += xs * w0.x; acc[1]  += xs * w0.y; acc[2]  += xs * w0.z; acc[3]  += xs * w0.w;
            acc[4]  += xs * w1.x; acc[5]  += xs * w1.y; acc[6]  += xs * w1.z; acc[7]  += xs * w1.w;
            acc[8]  += xs * w2.x; acc[9]  += xs * w2.y; acc[10] += xs * w2.z; acc[11] += xs * w2.w;
            acc[12] += xs * w3.x; acc[13] += xs * w3.y; acc[14] += xs * w3.z; acc[15] += xs * w3.w;
        }
    }

    int row = row0 + tid;
    if (row < n) {
        float4* hr = (float4*)(g_h1 + (size_t)row * NH);
        hr[0] = make_float4(acc[0], acc[1], acc[2], acc[3]);
        hr[1] = make_float4(acc[4], acc[5], acc[6], acc[7]);
        hr[2] = make_float4(acc[8], acc[9], acc[10], acc[11]);
        hr[3] = make_float4(acc[12], acc[13], acc[14], acc[15]);
    }
}

// ---------------------------------------------------------------------------
// Aggregation layer 1 (push): 4 lanes/edge, float4 vector atomics (sm_90+)
// ---------------------------------------------------------------------------
__global__ void k_agg1(const int* __restrict__ src,
                       const int* __restrict__ dst, int E) {
    int g = (blockIdx.x * blockDim.x + threadIdx.x) >> 2;
    int c4 = threadIdx.x & 3;
    if (g >= E) return;
    int s = src[g];
    int d = dst[g];
    float w = g_dinv[s] * g_dinv[d];
    float4 h = ((const float4*)(g_h1 + (size_t)s * NH))[c4];
    atomicAdd(((float4*)(g_a1 + (size_t)d * NH)) + c4,
              make_float4(w * h.x, w * h.y, w * h.z, w * h.w));
}

// self-loop term + relu
__global__ void k_post1(int n) {
    int i = blockIdx.x * blockDim.x + threadIdx.x;
    if (i >= n * NH) return;
    int d = i >> 4;
    float di = g_dinv[d];
    float v = g_a1[i] + di * di * g_h1[i];
    g_a1[i] = v > 0.0f ? v : 0.0f;
}

// ---------------------------------------------------------------------------
// Aggregation layer 2 (push, PRE-W2 thanks to linearity): aggregate 16-dim a1
// + scalar norm-sum for the bias term. 4 lanes/edge, float4 atomics.
// ---------------------------------------------------------------------------
__global__ void k_agg2(const int* __restrict__ src,
                       const int* __restrict__ dst, int E) {
    int g = (blockIdx.x * blockDim.x + threadIdx.x) >> 2;
    int c4 = threadIdx.x & 3;
    if (g >= E) return;
    int s = src[g];
    int d = dst[g];
    float w = g_dinv[s] * g_dinv[d];
    float4 h = ((const float4*)(g_a1 + (size_t)s * NH))[c4];
    atomicAdd(((float4*)(g_agg2 + (size_t)d * NH)) + c4,
              make_float4(w * h.x, w * h.y, w * h.z, w * h.w));
    if (c4 == 0) atomicAdd(&g_nsum[d], w);
}

// ---------------------------------------------------------------------------
// Fused: (agg2 + selfloop) @ W2 + nsum*b2  ->  log_softmax  ->  out
// Thread per row; W2 (16x40) broadcast from smem; float4 output writes.
// ---------------------------------------------------------------------------
__global__ void __launch_bounds__(128) k_final(const float* __restrict__ W2,
                                               const float* __restrict__ b2,
                                               float* __restrict__ out, int n) {
    __shared__ float sW[NH * NC];
    __shared__ float sb[NC];
    for (int i = threadIdx.x; i < NH * NC; i += blockDim.x) sW[i] = W2[i];
    if (threadIdx.x < NC) sb[threadIdx.x] = b2[threadIdx.x];
    __syncthreads();

    int r = blockIdx.x * blockDim.x + threadIdx.x;
    if (r >= n) return;

    float di = g_dinv[r];
    float d2 = di * di;
    float ns = g_nsum[r] + d2;  // + self-loop norm

    float tt[NH];
    const float4* ag = (const float4*)(g_agg2 + (size_t)r * NH);
    const float4* a1 = (const float4*)(g_a1 + (size_t)r * NH);
#pragma unroll
    for (int q = 0; q < 4; q++) {
        float4 A = ag[q], B = a1[q];
        tt[q * 4 + 0] = A.x + d2 * B.x;
        tt[q * 4 + 1] = A.y + d2 * B.y;
        tt[q * 4 + 2] = A.z + d2 * B.z;
        tt[q * 4 + 3] = A.w + d2 * B.w;
    }

    float v[NC];
#pragma unroll
    for (int c = 0; c < NC; c++) v[c] = ns * sb[c];
#pragma unroll
    for (int k = 0; k < NH; k++) {
        float tv = tt[k];
#pragma unroll
        for (int c = 0; c < NC; c++) v[c] += tv * sW[k * NC + c];
    }

    float m = v[0];
#pragma unroll
    for (int c = 1; c < NC; c++) m = fmaxf(m, v[c]);
    float s = 0.0f;
#pragma unroll
    for (int c = 0; c < NC; c++) s += expf(v[c] - m);
    float lse = m + logf(s);

    float4* orow = (float4*)(out + (size_t)r * NC);
#pragma unroll
    for (int q = 0; q < NC / 4; q++) {
        orow[q] = make_float4(v[q * 4 + 0] - lse, v[q * 4 + 1] - lse,
                              v[q * 4 + 2] - lse, v[q * 4 + 3] - lse);
    }
}

// ---------------------------------------------------------------------------
extern "C" void kernel_launch(void* const* d_in, const int* in_sizes, int n_in,
                              void* d_out, int out_size) {
    const float* x = (const float*)d_in[0];
    const int* ei = (const int*)d_in[1];     // int32 (JAX x64 disabled)
    const float* W1 = (const float*)d_in[2];
    const float* b1 = (const float*)d_in[3];
    const float* W2 = (const float*)d_in[4];
    const float* b2 = (const float*)d_in[5];
    float* out = (float*)d_out;

    int n = in_sizes[0] / NF;            // 100000
    int E = in_sizes[1] / 2;             // 3200000
    const int* src = ei;
    const int* dst = ei + E;

    const int B = 256;
    k_init<<<(n * NH + B - 1) / B, B>>>(n);
    k_deg<<<(E + B - 1) / B, B>>>(src, E);
    k_dinv<<<(n + B - 1) / B, B>>>(n);
    k_gemm1<<<(n + 127) / 128, 128>>>(x, W1, b1, n);
    {
        long long th = (long long)E * 4;
        k_agg1<<<(unsigned)((th + B - 1) / B), B>>>(src, dst, E);
    }
    k_post1<<<(n * NH + B - 1) / B, B>>>(n);
    {
        long long th = (long long)E * 4;
        k_agg2<<<(unsigned)((th + B - 1) / B), B>>>(src, dst, E);
    }
    k_final<<<(n + 127) / 128, 128>>>(W2, b2, out, n);
}

// round 7
// speedup vs baseline: 2.4704x; 1.1786x over previous
#include <cuda_runtime.h>

#define NF 512
#define NH 16
#define NC 40
#define NMAX 100000

// ---- scratch (static device globals; no allocations allowed) ----
__device__ float g_deg[NMAX];
__device__ float g_dinv[NMAX];
__device__ float g_h1[NMAX * NH];    // x @ W1 + b1
__device__ float g_a1[NMAX * NH];    // layer-1 aggregated + relu
__device__ float g_agg2[NMAX * NH];  // layer-2 aggregation of a1 (pre-W2!)
__device__ float g_nsum[NMAX];       // sum of norm over in-edges (for bias)

// packed fp32x2 FMA (Blackwell, PTX 8.6)
#define FFMA2(acc, a, b) \
    asm("fma.rn.f32x2 %0, %1, %2, %3;" : "=l"(acc) : "l"(a), "l"(b), "l"(acc))
#define PACK2(out, lo, hi) \
    asm("mov.b64 %0, {%1, %2};" : "=l"(out) : "f"(lo), "f"(hi))

// ---------------------------------------------------------------------------
// init: deg = 1 (self loop), zero accumulators
// ---------------------------------------------------------------------------
__global__ void k_init(int n) {
    int i = blockIdx.x * blockDim.x + threadIdx.x;
    if (i < n) { g_deg[i] = 1.0f; g_nsum[i] = 0.0f; }
    if (i < n * NH) { g_a1[i] = 0.0f; g_agg2[i] = 0.0f; }
}

// ---------------------------------------------------------------------------
// degree over src (row)
// ---------------------------------------------------------------------------
__global__ void k_deg(const int* __restrict__ src, int E) {
    int e = blockIdx.x * blockDim.x + threadIdx.x;
    if (e < E) atomicAdd(&g_deg[src[e]], 1.0f);
}

__global__ void k_dinv(int n) {
    int i = blockIdx.x * blockDim.x + threadIdx.x;
    if (i < n) g_dinv[i] = rsqrtf(g_deg[i]);
}

// ---------------------------------------------------------------------------
// GEMM1: h1 = x @ W1 + b1
//  - dynamic smem: sW (32KB, W1 resident) + xt (33.8KB x-tile, pad 33)
//  - x staged in k-tiles of 32 via register-prefetch pipeline (8 float4/thread)
//  - packed f32x2 FMAs: 8 FFMA2 per k instead of 16 FFMA
//  - block = 256 threads = 256 rows; 66.3KB -> 3 blocks/SM, single wave
// ---------------------------------------------------------------------------
#define GEMM1_SMEM ((NF * NH + 256 * 33) * sizeof(float))

__global__ void __launch_bounds__(256, 3) k_gemm1(const float* __restrict__ x,
                                                  const float* __restrict__ W1,
                                                  const float* __restrict__ b1, int n) {
    extern __shared__ float smem[];
    float* sW = smem;                 // NF*NH floats (32 KB)
    float* xt = smem + NF * NH;       // 256*33 floats (33.8 KB)
    int tid = threadIdx.x;
    int row0 = blockIdx.x * 256;
    int row = row0 + tid;

    // load W1 into smem (coalesced float4)
    {
        const float4* W4 = (const float4*)W1;
        float4* sW4 = (float4*)sW;
        for (int i = tid; i < NF * NH / 4; i += 256) sW4[i] = W4[i];
    }

    // packed accumulators, init from bias
    unsigned long long acc[8];
#pragma unroll
    for (int j = 0; j < 8; j++) {
        float lo = __ldg(&b1[2 * j]), hi = __ldg(&b1[2 * j + 1]);
        PACK2(acc[j], lo, hi);
    }

    const unsigned long long* sW2 = (const unsigned long long*)sW;
    const float4* xg = (const float4*)x;

    // prefetch tile 0 into registers
    float4 pf[8];
#pragma unroll
    for (int q = 0; q < 8; q++) {
        int f = q * 256 + tid;            // 0..2047
        int r = row0 + (f >> 3);          // row
        int c4 = f & 7;                   // float4 within 32-col tile
        pf[q] = (r < n) ? __ldg(&xg[(size_t)r * (NF / 4) + c4])
                        : make_float4(0.f, 0.f, 0.f, 0.f);
    }
    __syncthreads();  // sW ready

    for (int t = 0; t < NF / 32; t++) {
        // store prefetched tile to smem (scalar STS: conflict-free with pad 33)
#pragma unroll
        for (int q = 0; q < 8; q++) {
            int f = q * 256 + tid;
            int r = f >> 3, c4 = f & 7;
            float* dstp = &xt[r * 33 + c4 * 4];
            dstp[0] = pf[q].x; dstp[1] = pf[q].y; dstp[2] = pf[q].z; dstp[3] = pf[q].w;
        }
        // issue loads for next tile
        if (t + 1 < NF / 32) {
            int k0n = (t + 1) * 8;  // float4 offset of next tile
#pragma unroll
            for (int q = 0; q < 8; q++) {
                int f = q * 256 + tid;
                int r = row0 + (f >> 3);
                int c4 = f & 7;
                pf[q] = (r < n) ? __ldg(&xg[(size_t)r * (NF / 4) + k0n + c4])
                                : make_float4(0.f, 0.f, 0.f, 0.f);
            }
        }
        __syncthreads();  // tile t visible

        const unsigned long long* wk = sW2 + (size_t)t * 32 * 8;
        const float* xr = &xt[tid * 33];
#pragma unroll
        for (int k = 0; k < 32; k++) {
            float xs = xr[k];
            unsigned long long xx;
            PACK2(xx, xs, xs);
#pragma unroll
            for (int j = 0; j < 8; j++) {
                FFMA2(acc[j], xx, wk[k * 8 + j]);
            }
        }
        __syncthreads();  // done reading xt before next overwrite
    }

    if (row < n) {
        unsigned long long* hr = (unsigned long long*)(g_h1 + (size_t)row * NH);
#pragma unroll
        for (int j = 0; j < 8; j++) hr[j] = acc[j];
    }
}

// ---------------------------------------------------------------------------
// Aggregation layer 1 (push): 4 lanes/edge, float4 vector atomics
// ---------------------------------------------------------------------------
__global__ void k_agg1(const int* __restrict__ src,
                       const int* __restrict__ dst, int E) {
    int g = (blockIdx.x * blockDim.x + threadIdx.x) >> 2;
    int c4 = threadIdx.x & 3;
    if (g >= E) return;
    int s = src[g];
    int d = dst[g];
    float w = g_dinv[s] * g_dinv[d];
    float4 h = ((const float4*)(g_h1 + (size_t)s * NH))[c4];
    atomicAdd(((float4*)(g_a1 + (size_t)d * NH)) + c4,
              make_float4(w * h.x, w * h.y, w * h.z, w * h.w));
}

// self-loop term + relu
__global__ void k_post1(int n) {
    int i = blockIdx.x * blockDim.x + threadIdx.x;
    if (i >= n * NH) return;
    int d = i >> 4;
    float di = g_dinv[d];
    float v = g_a1[i] + di * di * g_h1[i];
    g_a1[i] = v > 0.0f ? v : 0.0f;
}

// ---------------------------------------------------------------------------
// Aggregation layer 2 (push, PRE-W2 via linearity): aggregate 16-dim a1
// + scalar norm-sum for the bias term. 4 lanes/edge, float4 atomics.
// ---------------------------------------------------------------------------
__global__ void k_agg2(const int* __restrict__ src,
                       const int* __restrict__ dst, int E) {
    int g = (blockIdx.x * blockDim.x + threadIdx.x) >> 2;
    int c4 = threadIdx.x & 3;
    if (g >= E) return;
    int s = src[g];
    int d = dst[g];
    float w = g_dinv[s] * g_dinv[d];
    float4 h = ((const float4*)(g_a1 + (size_t)s * NH))[c4];
    atomicAdd(((float4*)(g_agg2 + (size_t)d * NH)) + c4,
              make_float4(w * h.x, w * h.y, w * h.z, w * h.w));
    if (c4 == 0) atomicAdd(&g_nsum[d], w);
}

// ---------------------------------------------------------------------------
// Fused: (agg2 + selfloop) @ W2 + nsum*b2  ->  log_softmax  ->  out
// ---------------------------------------------------------------------------
__global__ void __launch_bounds__(128) k_final(const float* __restrict__ W2,
                                               const float* __restrict__ b2,
                                               float* __restrict__ out, int n) {
    __shared__ float sW[NH * NC];
    __shared__ float sb[NC];
    for (int i = threadIdx.x; i < NH * NC; i += blockDim.x) sW[i] = W2[i];
    if (threadIdx.x < NC) sb[threadIdx.x] = b2[threadIdx.x];
    __syncthreads();

    int r = blockIdx.x * blockDim.x + threadIdx.x;
    if (r >= n) return;

    float di = g_dinv[r];
    float d2 = di * di;
    float ns = g_nsum[r] + d2;  // + self-loop norm

    float tt[NH];
    const float4* ag = (const float4*)(g_agg2 + (size_t)r * NH);
    const float4* a1 = (const float4*)(g_a1 + (size_t)r * NH);
#pragma unroll
    for (int q = 0; q < 4; q++) {
        float4 A = ag[q], B = a1[q];
        tt[q * 4 + 0] = A.x + d2 * B.x;
        tt[q * 4 + 1] = A.y + d2 * B.y;
        tt[q * 4 + 2] = A.z + d2 * B.z;
        tt[q * 4 + 3] = A.w + d2 * B.w;
    }

    float v[NC];
#pragma unroll
    for (int c = 0; c < NC; c++) v[c] = ns * sb[c];
#pragma unroll
    for (int k = 0; k < NH; k++) {
        float tv = tt[k];
#pragma unroll
        for (int c = 0; c < NC; c++) v[c] += tv * sW[k * NC + c];
    }

    float m = v[0];
#pragma unroll
    for (int c = 1; c < NC; c++) m = fmaxf(m, v[c]);
    float s = 0.0f;
#pragma unroll
    for (int c = 0; c < NC; c++) s += expf(v[c] - m);
    float lse = m + logf(s);

    float4* orow = (float4*)(out + (size_t)r * NC);
#pragma unroll
    for (int q = 0; q < NC / 4; q++) {
        orow[q] = make_float4(v[q * 4 + 0] - lse, v[q * 4 + 1] - lse,
                              v[q * 4 + 2] - lse, v[q * 4 + 3] - lse);
    }
}

// ---------------------------------------------------------------------------
extern "C" void kernel_launch(void* const* d_in, const int* in_sizes, int n_in,
                              void* d_out, int out_size) {
    const float* x = (const float*)d_in[0];
    const int* ei = (const int*)d_in[1];     // int32 (JAX x64 disabled)
    const float* W1 = (const float*)d_in[2];
    const float* b1 = (const float*)d_in[3];
    const float* W2 = (const float*)d_in[4];
    const float* b2 = (const float*)d_in[5];
    float* out = (float*)d_out;

    int n = in_sizes[0] / NF;            // 100000
    int E = in_sizes[1] / 2;             // 3200000
    const int* src = ei;
    const int* dst = ei + E;

    // opt-in to >48KB dynamic smem (host-side attribute; not a stream op,
    // not an allocation; idempotent and legal during graph capture)
    cudaFuncSetAttribute(k_gemm1, cudaFuncAttributeMaxDynamicSharedMemorySize,
                         (int)GEMM1_SMEM);

    const int B = 256;
    k_init<<<(n * NH + B - 1) / B, B>>>(n);
    k_deg<<<(E + B - 1) / B, B>>>(src, E);
    k_dinv<<<(n + B - 1) / B, B>>>(n);
    k_gemm1<<<(n + 255) / 256, 256, GEMM1_SMEM>>>(x, W1, b1, n);
    {
        long long th = (long long)E * 4;
        k_agg1<<<(unsigned)((th + B - 1) / B), B>>>(src, dst, E);
    }
    k_post1<<<(n * NH + B - 1) / B, B>>>(n);
    {
        long long th = (long long)E * 4;
        k_agg2<<<(unsigned)((th + B - 1) / B), B>>>(src, dst, E);
    }
    k_final<<<(n + 127) / 128, 128>>>(W2, b2, out, n);
}

// round 8
// speedup vs baseline: 2.5209x; 1.0204x over previous
#include <cuda_runtime.h>

#define NF 512
#define NH 16
#define NC 40
#define NMAX 100000

// ---- scratch (static device globals; no allocations allowed) ----
__device__ float g_deg[NMAX];
__device__ float g_dinv[NMAX];
__device__ float g_h1[NMAX * NH];    // x @ W1 + b1
__device__ float g_a1[NMAX * NH];    // layer-1 aggregated + relu
__device__ float g_agg2[NMAX * NH];  // layer-2 aggregation of a1 (pre-W2!)
__device__ float g_nsum[NMAX];       // sum of norm over in-edges (for bias)

// packed fp32x2 FMA (Blackwell, PTX 8.6)
#define FFMA2(acc, a, b) \
    asm("fma.rn.f32x2 %0, %1, %2, %3;" : "=l"(acc) : "l"(a), "l"(b), "l"(acc))
#define PACK2(out, lo, hi) \
    asm("mov.b64 %0, {%1, %2};" : "=l"(out) : "f"(lo), "f"(hi))

// ---------------------------------------------------------------------------
// init: deg = 1 (self loop), zero accumulators
// ---------------------------------------------------------------------------
__global__ void k_init(int n) {
    int i = blockIdx.x * blockDim.x + threadIdx.x;
    if (i < n) { g_deg[i] = 1.0f; g_nsum[i] = 0.0f; }
    if (i < n * NH) { g_a1[i] = 0.0f; g_agg2[i] = 0.0f; }
}

__global__ void k_dinv(int n) {
    int i = blockIdx.x * blockDim.x + threadIdx.x;
    if (i < n) g_dinv[i] = rsqrtf(g_deg[i]);
}

// ---------------------------------------------------------------------------
// GEMM1: h1 = x @ W1 + b1   (+ fused degree pass in epilogue)
//  - dynamic smem: sW (32KB, W1 resident) + xt (36KB x-tile, pad 36)
//  - all 128-bit smem traffic: STS.128 stores, float4 x reads,
//    ulonglong2 (LDS.128 broadcast) W reads -> 4 W wavefronts/k instead of 8
//  - packed f32x2 FMAs: 8 FFMA2 per k
//  - epilogue: grid-stride degree atomics (overlaps deg kernel into gemm tail)
// ---------------------------------------------------------------------------
#define GEMM1_SMEM ((NF * NH + 256 * 36) * sizeof(float))

__global__ void __launch_bounds__(256, 3) k_gemm1(const float* __restrict__ x,
                                                  const float* __restrict__ W1,
                                                  const float* __restrict__ b1,
                                                  const int* __restrict__ src,
                                                  int n, int E) {
    extern __shared__ float smem[];
    float* sW = smem;                 // NF*NH floats (32 KB)
    float* xt = smem + NF * NH;       // 256*36 floats (36 KB)
    int tid = threadIdx.x;
    int row0 = blockIdx.x * 256;
    int row = row0 + tid;

    // load W1 into smem (coalesced float4)
    {
        const float4* W4 = (const float4*)W1;
        float4* sW4 = (float4*)sW;
        for (int i = tid; i < NF * NH / 4; i += 256) sW4[i] = W4[i];
    }

    // packed accumulators, init from bias
    unsigned long long acc[8];
#pragma unroll
    for (int j = 0; j < 8; j++) {
        float lo = __ldg(&b1[2 * j]), hi = __ldg(&b1[2 * j + 1]);
        PACK2(acc[j], lo, hi);
    }

    const float4* xg = (const float4*)x;

    // prefetch tile 0 into registers
    float4 pf[8];
#pragma unroll
    for (int q = 0; q < 8; q++) {
        int f = q * 256 + tid;            // 0..2047
        int r = row0 + (f >> 3);          // row
        int c4 = f & 7;                   // float4 within 32-col tile
        pf[q] = (r < n) ? __ldg(&xg[(size_t)r * (NF / 4) + c4])
                        : make_float4(0.f, 0.f, 0.f, 0.f);
    }
    __syncthreads();  // sW ready

    for (int t = 0; t < NF / 32; t++) {
        // STS.128 tile store (conflict-free: banks 4*c4.. cover all 32)
#pragma unroll
        for (int q = 0; q < 8; q++) {
            int f = q * 256 + tid;
            int r = f >> 3, c4 = f & 7;
            *(float4*)(&xt[r * 36 + c4 * 4]) = pf[q];
        }
        // issue loads for next tile
        if (t + 1 < NF / 32) {
            int k0n = (t + 1) * 8;  // float4 offset of next tile
#pragma unroll
            for (int q = 0; q < 8; q++) {
                int f = q * 256 + tid;
                int r = row0 + (f >> 3);
                int c4 = f & 7;
                pf[q] = (r < n) ? __ldg(&xg[(size_t)r * (NF / 4) + k0n + c4])
                                : make_float4(0.f, 0.f, 0.f, 0.f);
            }
        }
        __syncthreads();  // tile t visible

        const ulonglong2* wk = (const ulonglong2*)(sW + (size_t)t * 32 * NH);
        const float* xr = &xt[tid * 36];
#pragma unroll
        for (int kq = 0; kq < 8; kq++) {
            float4 xv = *(const float4*)(xr + kq * 4);  // LDS.128, conflict-free
#pragma unroll
            for (int j = 0; j < 4; j++) {
                int k = kq * 4 + j;
                float xs = (&xv.x)[j];
                unsigned long long xx;
                PACK2(xx, xs, xs);
                ulonglong2 wa = wk[k * 4 + 0];  // LDS.128 broadcast
                ulonglong2 wb = wk[k * 4 + 1];
                ulonglong2 wc = wk[k * 4 + 2];
                ulonglong2 wd = wk[k * 4 + 3];
                FFMA2(acc[0], xx, wa.x); FFMA2(acc[1], xx, wa.y);
                FFMA2(acc[2], xx, wb.x); FFMA2(acc[3], xx, wb.y);
                FFMA2(acc[4], xx, wc.x); FFMA2(acc[5], xx, wc.y);
                FFMA2(acc[6], xx, wd.x); FFMA2(acc[7], xx, wd.y);
            }
        }
        __syncthreads();  // done reading xt before next overwrite
    }

    if (row < n) {
        unsigned long long* hr = (unsigned long long*)(g_h1 + (size_t)row * NH);
#pragma unroll
        for (int j = 0; j < 8; j++) hr[j] = acc[j];
    }

    // fused degree pass (grid-stride; overlaps into gemm memory slack)
    int stride = gridDim.x * 256;
    for (int e = blockIdx.x * 256 + tid; e < E; e += stride)
        atomicAdd(&g_deg[src[e]], 1.0f);
}

// ---------------------------------------------------------------------------
// Aggregation layer 1 (push): 4 lanes/edge, float4 vector atomics
// ---------------------------------------------------------------------------
__global__ void k_agg1(const int* __restrict__ src,
                       const int* __restrict__ dst, int E) {
    int g = (blockIdx.x * blockDim.x + threadIdx.x) >> 2;
    int c4 = threadIdx.x & 3;
    if (g >= E) return;
    int s = src[g];
    int d = dst[g];
    float w = g_dinv[s] * g_dinv[d];
    float4 h = ((const float4*)(g_h1 + (size_t)s * NH))[c4];
    atomicAdd(((float4*)(g_a1 + (size_t)d * NH)) + c4,
              make_float4(w * h.x, w * h.y, w * h.z, w * h.w));
}

// self-loop term + relu
__global__ void k_post1(int n) {
    int i = blockIdx.x * blockDim.x + threadIdx.x;
    if (i >= n * NH) return;
    int d = i >> 4;
    float di = g_dinv[d];
    float v = g_a1[i] + di * di * g_h1[i];
    g_a1[i] = v > 0.0f ? v : 0.0f;
}

// ---------------------------------------------------------------------------
// Aggregation layer 2 (push, PRE-W2 via linearity): aggregate 16-dim a1
// + scalar norm-sum for the bias term. 4 lanes/edge, float4 atomics.
// ---------------------------------------------------------------------------
__global__ void k_agg2(const int* __restrict__ src,
                       const int* __restrict__ dst, int E) {
    int g = (blockIdx.x * blockDim.x + threadIdx.x) >> 2;
    int c4 = threadIdx.x & 3;
    if (g >= E) return;
    int s = src[g];
    int d = dst[g];
    float w = g_dinv[s] * g_dinv[d];
    float4 h = ((const float4*)(g_a1 + (size_t)s * NH))[c4];
    atomicAdd(((float4*)(g_agg2 + (size_t)d * NH)) + c4,
              make_float4(w * h.x, w * h.y, w * h.z, w * h.w));
    if (c4 == 0) atomicAdd(&g_nsum[d], w);
}

// ---------------------------------------------------------------------------
// Fused: (agg2 + selfloop) @ W2 + nsum*b2  ->  log_softmax  ->  out
// ---------------------------------------------------------------------------
__global__ void __launch_bounds__(128) k_final(const float* __restrict__ W2,
                                               const float* __restrict__ b2,
                                               float* __restrict__ out, int n) {
    __shared__ float sW[NH * NC];
    __shared__ float sb[NC];
    for (int i = threadIdx.x; i < NH * NC; i += blockDim.x) sW[i] = W2[i];
    if (threadIdx.x < NC) sb[threadIdx.x] = b2[threadIdx.x];
    __syncthreads();

    int r = blockIdx.x * blockDim.x + threadIdx.x;
    if (r >= n) return;

    float di = g_dinv[r];
    float d2 = di * di;
    float ns = g_nsum[r] + d2;  // + self-loop norm

    float tt[NH];
    const float4* ag = (const float4*)(g_agg2 + (size_t)r * NH);
    const float4* a1 = (const float4*)(g_a1 + (size_t)r * NH);
#pragma unroll
    for (int q = 0; q < 4; q++) {
        float4 A = ag[q], B = a1[q];
        tt[q * 4 + 0] = A.x + d2 * B.x;
        tt[q * 4 + 1] = A.y + d2 * B.y;
        tt[q * 4 + 2] = A.z + d2 * B.z;
        tt[q * 4 + 3] = A.w + d2 * B.w;
    }

    float v[NC];
#pragma unroll
    for (int c = 0; c < NC; c++) v[c] = ns * sb[c];
#pragma unroll
    for (int k = 0; k < NH; k++) {
        float tv = tt[k];
#pragma unroll
        for (int c = 0; c < NC; c++) v[c] += tv * sW[k * NC + c];
    }

    float m = v[0];
#pragma unroll
    for (int c = 1; c < NC; c++) m = fmaxf(m, v[c]);
    float s = 0.0f;
#pragma unroll
    for (int c = 0; c < NC; c++) s += expf(v[c] - m);
    float lse = m + logf(s);

    float4* orow = (float4*)(out + (size_t)r * NC);
#pragma unroll
    for (int q = 0; q < NC / 4; q++) {
        orow[q] = make_float4(v[q * 4 + 0] - lse, v[q * 4 + 1] - lse,
                              v[q * 4 + 2] - lse, v[q * 4 + 3] - lse);
    }
}

// ---------------------------------------------------------------------------
extern "C" void kernel_launch(void* const* d_in, const int* in_sizes, int n_in,
                              void* d_out, int out_size) {
    const float* x = (const float*)d_in[0];
    const int* ei = (const int*)d_in[1];     // int32 (JAX x64 disabled)
    const float* W1 = (const float*)d_in[2];
    const float* b1 = (const float*)d_in[3];
    const float* W2 = (const float*)d_in[4];
    const float* b2 = (const float*)d_in[5];
    float* out = (float*)d_out;

    int n = in_sizes[0] / NF;            // 100000
    int E = in_sizes[1] / 2;             // 3200000
    const int* src = ei;
    const int* dst = ei + E;

    // opt-in to >48KB dynamic smem (host-side attribute; idempotent,
    // legal during graph capture, not an allocation)
    cudaFuncSetAttribute(k_gemm1, cudaFuncAttributeMaxDynamicSharedMemorySize,
                         (int)GEMM1_SMEM);

    const int B = 256;
    k_init<<<(n * NH + B - 1) / B, B>>>(n);
    k_gemm1<<<(n + 255) / 256, 256, GEMM1_SMEM>>>(x, W1, b1, src, n, E);
    k_dinv<<<(n + B - 1) / B, B>>>(n);
    {
        long long th = (long long)E * 4;
        k_agg1<<<(unsigned)((th + B - 1) / B), B>>>(src, dst, E);
    }
    k_post1<<<(n * NH + B - 1) / B, B>>>(n);
    {
        long long th = (long long)E * 4;
        k_agg2<<<(unsigned)((th + B - 1) / B), B>>>(src, dst, E);
    }
    k_final<<<(n + 127) / 128, 128>>>(W2, b2, out, n);
}

// round 9
// speedup vs baseline: 2.7457x; 1.0892x over previous
#include <cuda_runtime.h>

#define NF 512
#define NH 16
#define NC 40
#define NMAX 100000

// ---- scratch (static device globals; no allocations allowed) ----
__device__ float g_deg[NMAX];
__device__ float g_dinv[NMAX];
__device__ float g_h1[NMAX * NH];    // x@W1+b1, then scaled in place: h1s = dinv*h1
__device__ float g_a1[NMAX * NH];    // layer-1 raw aggregation of h1s
__device__ float g_a1s[NMAX * NH];   // dinv * relu(layer-1 output)
__device__ float g_agg2[NMAX * NH];  // layer-2 raw aggregation of a1s
__device__ float g_nsum[NMAX];       // raw sum of dinv[s] over in-edges

// packed fp32x2 FMA (Blackwell, PTX 8.6)
#define FFMA2(acc, a, b) \
    asm("fma.rn.f32x2 %0, %1, %2, %3;" : "=l"(acc) : "l"(a), "l"(b), "l"(acc))
#define PACK2(out, lo, hi) \
    asm("mov.b64 %0, {%1, %2};" : "=l"(out) : "f"(lo), "f"(hi))

// ---------------------------------------------------------------------------
// init: deg = 1 (self loop), zero accumulators
// ---------------------------------------------------------------------------
__global__ void k_init(int n) {
    int i = blockIdx.x * blockDim.x + threadIdx.x;
    if (i < n) { g_deg[i] = 1.0f; g_nsum[i] = 0.0f; }
    if (i < n * NH) { g_a1[i] = 0.0f; g_agg2[i] = 0.0f; }
}

// ---------------------------------------------------------------------------
// dinv + pre-scale h1 in place (h1s = dinv * h1)
// ---------------------------------------------------------------------------
__global__ void k_dinv_scale(int n) {
    int r = blockIdx.x * blockDim.x + threadIdx.x;
    if (r >= n) return;
    float di = rsqrtf(g_deg[r]);
    g_dinv[r] = di;
    float4* h = (float4*)(g_h1 + (size_t)r * NH);
#pragma unroll
    for (int q = 0; q < 4; q++) {
        float4 v = h[q];
        h[q] = make_float4(di * v.x, di * v.y, di * v.z, di * v.w);
    }
}

// ---------------------------------------------------------------------------
// GEMM1: h1 = x @ W1 + b1   (+ fused degree pass in epilogue)
// ---------------------------------------------------------------------------
#define GEMM1_SMEM ((NF * NH + 256 * 36) * sizeof(float))

__global__ void __launch_bounds__(256, 3) k_gemm1(const float* __restrict__ x,
                                                  const float* __restrict__ W1,
                                                  const float* __restrict__ b1,
                                                  const int* __restrict__ src,
                                                  int n, int E) {
    extern __shared__ float smem[];
    float* sW = smem;                 // NF*NH floats (32 KB)
    float* xt = smem + NF * NH;       // 256*36 floats (36 KB)
    int tid = threadIdx.x;
    int row0 = blockIdx.x * 256;
    int row = row0 + tid;

    {
        const float4* W4 = (const float4*)W1;
        float4* sW4 = (float4*)sW;
        for (int i = tid; i < NF * NH / 4; i += 256) sW4[i] = W4[i];
    }

    unsigned long long acc[8];
#pragma unroll
    for (int j = 0; j < 8; j++) {
        float lo = __ldg(&b1[2 * j]), hi = __ldg(&b1[2 * j + 1]);
        PACK2(acc[j], lo, hi);
    }

    const float4* xg = (const float4*)x;

    float4 pf[8];
#pragma unroll
    for (int q = 0; q < 8; q++) {
        int f = q * 256 + tid;
        int r = row0 + (f >> 3);
        int c4 = f & 7;
        pf[q] = (r < n) ? __ldg(&xg[(size_t)r * (NF / 4) + c4])
                        : make_float4(0.f, 0.f, 0.f, 0.f);
    }
    __syncthreads();

    for (int t = 0; t < NF / 32; t++) {
#pragma unroll
        for (int q = 0; q < 8; q++) {
            int f = q * 256 + tid;
            int r = f >> 3, c4 = f & 7;
            *(float4*)(&xt[r * 36 + c4 * 4]) = pf[q];
        }
        if (t + 1 < NF / 32) {
            int k0n = (t + 1) * 8;
#pragma unroll
            for (int q = 0; q < 8; q++) {
                int f = q * 256 + tid;
                int r = row0 + (f >> 3);
                int c4 = f & 7;
                pf[q] = (r < n) ? __ldg(&xg[(size_t)r * (NF / 4) + k0n + c4])
                                : make_float4(0.f, 0.f, 0.f, 0.f);
            }
        }
        __syncthreads();

        const ulonglong2* wk = (const ulonglong2*)(sW + (size_t)t * 32 * NH);
        const float* xr = &xt[tid * 36];
#pragma unroll
        for (int kq = 0; kq < 8; kq++) {
            float4 xv = *(const float4*)(xr + kq * 4);
#pragma unroll
            for (int j = 0; j < 4; j++) {
                int k = kq * 4 + j;
                float xs = (&xv.x)[j];
                unsigned long long xx;
                PACK2(xx, xs, xs);
                ulonglong2 wa = wk[k * 4 + 0];
                ulonglong2 wb = wk[k * 4 + 1];
                ulonglong2 wc = wk[k * 4 + 2];
                ulonglong2 wd = wk[k * 4 + 3];
                FFMA2(acc[0], xx, wa.x); FFMA2(acc[1], xx, wa.y);
                FFMA2(acc[2], xx, wb.x); FFMA2(acc[3], xx, wb.y);
                FFMA2(acc[4], xx, wc.x); FFMA2(acc[5], xx, wc.y);
                FFMA2(acc[6], xx, wd.x); FFMA2(acc[7], xx, wd.y);
            }
        }
        __syncthreads();
    }

    if (row < n) {
        unsigned long long* hr = (unsigned long long*)(g_h1 + (size_t)row * NH);
#pragma unroll
        for (int j = 0; j < 8; j++) hr[j] = acc[j];
    }

    // fused degree pass (grid-stride)
    int stride = gridDim.x * 256;
    for (int e = blockIdx.x * 256 + tid; e < E; e += stride)
        atomicAdd(&g_deg[src[e]], 1.0f);
}

// ---------------------------------------------------------------------------
// Aggregation layer 1: pure gather + float4 atomic (weights pre-folded!)
// ---------------------------------------------------------------------------
__global__ void k_agg1(const int* __restrict__ src,
                       const int* __restrict__ dst, int E) {
    int g = (blockIdx.x * blockDim.x + threadIdx.x) >> 2;
    int c4 = threadIdx.x & 3;
    if (g >= E) return;
    int s = src[g];
    int d = dst[g];
    float4 h = ((const float4*)(g_h1 + (size_t)s * NH))[c4];
    atomicAdd(((float4*)(g_a1 + (size_t)d * NH)) + c4, h);
}

// a1s = dinv * relu(dinv * (a1raw + h1s))   [self term folded: d2*h1 = dinv*h1s]
__global__ void k_post1(int n) {
    int i = blockIdx.x * blockDim.x + threadIdx.x;
    if (i >= n * NH) return;
    float di = g_dinv[i >> 4];
    float v = di * (g_a1[i] + g_h1[i]);
    g_a1s[i] = di * fmaxf(v, 0.0f);
}

// ---------------------------------------------------------------------------
// Aggregation layer 2: gather + atomic; scalar dinv[s] sum for bias weight
// ---------------------------------------------------------------------------
__global__ void k_agg2(const int* __restrict__ src,
                       const int* __restrict__ dst, int E) {
    int g = (blockIdx.x * blockDim.x + threadIdx.x) >> 2;
    int c4 = threadIdx.x & 3;
    if (g >= E) return;
    int s = src[g];
    int d = dst[g];
    float4 h = ((const float4*)(g_a1s + (size_t)s * NH))[c4];
    atomicAdd(((float4*)(g_agg2 + (size_t)d * NH)) + c4, h);
    if (c4 == 0) atomicAdd(&g_nsum[d], g_dinv[s]);
}

// ---------------------------------------------------------------------------
// Fused: t = dinv*(agg2raw + a1s);  ns = dinv*(nsumraw + dinv)
//        logits = ns*b2 + t@W2  ->  log_softmax  ->  out
// ---------------------------------------------------------------------------
__global__ void __launch_bounds__(128) k_final(const float* __restrict__ W2,
                                               const float* __restrict__ b2,
                                               float* __restrict__ out, int n) {
    __shared__ float sW[NH * NC];
    __shared__ float sb[NC];
    for (int i = threadIdx.x; i < NH * NC; i += blockDim.x) sW[i] = W2[i];
    if (threadIdx.x < NC) sb[threadIdx.x] = b2[threadIdx.x];
    __syncthreads();

    int r = blockIdx.x * blockDim.x + threadIdx.x;
    if (r >= n) return;

    float di = g_dinv[r];
    float ns = di * (g_nsum[r] + di);

    float tt[NH];
    const float4* ag = (const float4*)(g_agg2 + (size_t)r * NH);
    const float4* as = (const float4*)(g_a1s + (size_t)r * NH);
#pragma unroll
    for (int q = 0; q < 4; q++) {
        float4 A = ag[q], B = as[q];
        tt[q * 4 + 0] = di * (A.x + B.x);
        tt[q * 4 + 1] = di * (A.y + B.y);
        tt[q * 4 + 2] = di * (A.z + B.z);
        tt[q * 4 + 3] = di * (A.w + B.w);
    }

    float v[NC];
#pragma unroll
    for (int c = 0; c < NC; c++) v[c] = ns * sb[c];
#pragma unroll
    for (int k = 0; k < NH; k++) {
        float tv = tt[k];
#pragma unroll
        for (int c = 0; c < NC; c++) v[c] += tv * sW[k * NC + c];
    }

    float m = v[0];
#pragma unroll
    for (int c = 1; c < NC; c++) m = fmaxf(m, v[c]);
    float s = 0.0f;
#pragma unroll
    for (int c = 0; c < NC; c++) s += expf(v[c] - m);
    float lse = m + logf(s);

    float4* orow = (float4*)(out + (size_t)r * NC);
#pragma unroll
    for (int q = 0; q < NC / 4; q++) {
        orow[q] = make_float4(v[q * 4 + 0] - lse, v[q * 4 + 1] - lse,
                              v[q * 4 + 2] - lse, v[q * 4 + 3] - lse);
    }
}

// ---------------------------------------------------------------------------
extern "C" void kernel_launch(void* const* d_in, const int* in_sizes, int n_in,
                              void* d_out, int out_size) {
    const float* x = (const float*)d_in[0];
    const int* ei = (const int*)d_in[1];     // int32 (JAX x64 disabled)
    const float* W1 = (const float*)d_in[2];
    const float* b1 = (const float*)d_in[3];
    const float* W2 = (const float*)d_in[4];
    const float* b2 = (const float*)d_in[5];
    float* out = (float*)d_out;

    int n = in_sizes[0] / NF;            // 100000
    int E = in_sizes[1] / 2;             // 3200000
    const int* src = ei;
    const int* dst = ei + E;

    cudaFuncSetAttribute(k_gemm1, cudaFuncAttributeMaxDynamicSharedMemorySize,
                         (int)GEMM1_SMEM);

    const int B = 256;
    k_init<<<(n * NH + B - 1) / B, B>>>(n);
    k_gemm1<<<(n + 255) / 256, 256, GEMM1_SMEM>>>(x, W1, b1, src, n, E);
    k_dinv_scale<<<(n + B - 1) / B, B>>>(n);
    {
        long long th = (long long)E * 4;
        k_agg1<<<(unsigned)((th + B - 1) / B), B>>>(src, dst, E);
    }
    k_post1<<<(n * NH + B - 1) / B, B>>>(n);
    {
        long long th = (long long)E * 4;
        k_agg2<<<(unsigned)((th + B - 1) / B), B>>>(src, dst, E);
    }
    k_final<<<(n + 127) / 128, 128>>>(W2, b2, out, n);
}